// round 7
// baseline (speedup 1.0000x reference)
#include <cuda_runtime.h>
#include <cuda_bf16.h>
#include <cstdint>

// Problem dims (fixed)
#define S_DIM 4096
#define C_DIM 2048
#define H_DIM 16
#define D_DIM 128
#define EPS_RMS 1.1920929e-07f

// ---------------------------------------------------------------------------
// Scratch (allocation-free rule: __device__ globals)
// ---------------------------------------------------------------------------
__device__ float g_Q[S_DIM * C_DIM];
__device__ float g_K[S_DIM * C_DIM];
__device__ float g_V[S_DIM * C_DIM];
__device__ float g_O[S_DIM * C_DIM];

// ---------------------------------------------------------------------------
// GEMM core: Out[M,N] = A[M,K] @ B[N,K]^T + bias[N]
// 128x128 block tile, BK=16, 256 threads, 8x8 microtile.
// Ping-pong smem double buffering: ONE __syncthreads per K-step.
// B fragment split into two 4-wide halves (tn*4 and 64+tn*4): per-phase
// quads distinct -> conflict-free LDS.128.
// ---------------------------------------------------------------------------
__device__ __forceinline__ void gemm_body(
    const float* __restrict__ A, const float* __restrict__ B,
    const float* __restrict__ bias, float* __restrict__ Out,
    int K, int N, int m0, int n0,
    float As[2][16][132], float Bs[2][16][132])
{
    const int tid = threadIdx.x;
    const int tm = tid >> 4;   // 0..15 -> rows tm*8..tm*8+7
    const int tn = tid & 15;   // 0..15 -> cols tn*4..+3 and 64+tn*4..+3

    float acc[8][8];
#pragma unroll
    for (int i = 0; i < 8; i++)
#pragma unroll
        for (int j = 0; j < 8; j++) acc[i][j] = 0.f;

    const float* Aptr = A + (size_t)m0 * K;
    const float* Bptr = B + (size_t)n0 * K;

    int lrow[2], lkv[2];
#pragma unroll
    for (int r = 0; r < 2; r++) {
        int idx = tid + r * 256;
        lrow[r] = idx >> 2;
        lkv[r]  = (idx & 3) << 2;
    }

    // Prologue: load first tile into buffer 0
#pragma unroll
    for (int r = 0; r < 2; r++) {
        float4 a = *reinterpret_cast<const float4*>(Aptr + (size_t)lrow[r] * K + lkv[r]);
        As[0][lkv[r] + 0][lrow[r]] = a.x; As[0][lkv[r] + 1][lrow[r]] = a.y;
        As[0][lkv[r] + 2][lrow[r]] = a.z; As[0][lkv[r] + 3][lrow[r]] = a.w;
        float4 b = *reinterpret_cast<const float4*>(Bptr + (size_t)lrow[r] * K + lkv[r]);
        Bs[0][lkv[r] + 0][lrow[r]] = b.x; Bs[0][lkv[r] + 1][lrow[r]] = b.y;
        Bs[0][lkv[r] + 2][lrow[r]] = b.z; Bs[0][lkv[r] + 3][lrow[r]] = b.w;
    }
    __syncthreads();

    int buf = 0;
    for (int k0 = 0; k0 < K; k0 += 16) {
        const int kn = k0 + 16;
        float4 pa[2], pb[2];
        if (kn < K) {
#pragma unroll
            for (int r = 0; r < 2; r++) {
                pa[r] = *reinterpret_cast<const float4*>(Aptr + (size_t)lrow[r] * K + kn + lkv[r]);
                pb[r] = *reinterpret_cast<const float4*>(Bptr + (size_t)lrow[r] * K + kn + lkv[r]);
            }
        }

#pragma unroll
        for (int kk = 0; kk < 16; kk++) {
            float4 a0 = *reinterpret_cast<const float4*>(&As[buf][kk][tm * 8]);
            float4 a1 = *reinterpret_cast<const float4*>(&As[buf][kk][tm * 8 + 4]);
            float4 b0 = *reinterpret_cast<const float4*>(&Bs[buf][kk][tn * 4]);
            float4 b1 = *reinterpret_cast<const float4*>(&Bs[buf][kk][64 + tn * 4]);
            float af[8] = {a0.x, a0.y, a0.z, a0.w, a1.x, a1.y, a1.z, a1.w};
            float bf[8] = {b0.x, b0.y, b0.z, b0.w, b1.x, b1.y, b1.z, b1.w};
#pragma unroll
            for (int i = 0; i < 8; i++)
#pragma unroll
                for (int j = 0; j < 8; j++)
                    acc[i][j] = fmaf(af[i], bf[j], acc[i][j]);
        }

        if (kn < K) {
            const int nb = buf ^ 1;   // write other buffer: no race with readers of buf
#pragma unroll
            for (int r = 0; r < 2; r++) {
                As[nb][lkv[r] + 0][lrow[r]] = pa[r].x; As[nb][lkv[r] + 1][lrow[r]] = pa[r].y;
                As[nb][lkv[r] + 2][lrow[r]] = pa[r].z; As[nb][lkv[r] + 3][lrow[r]] = pa[r].w;
                Bs[nb][lkv[r] + 0][lrow[r]] = pb[r].x; Bs[nb][lkv[r] + 1][lrow[r]] = pb[r].y;
                Bs[nb][lkv[r] + 2][lrow[r]] = pb[r].z; Bs[nb][lkv[r] + 3][lrow[r]] = pb[r].w;
            }
        }
        __syncthreads();
        buf ^= 1;
    }

    // Epilogue with bias, float4 stores (two column groups: tn*4 and 64+tn*4)
#pragma unroll
    for (int i = 0; i < 8; i++) {
        size_t orow = (size_t)(m0 + tm * 8 + i) * N + n0;
#pragma unroll
        for (int half = 0; half < 2; half++) {
            int cbase = half * 64 + tn * 4;
            float4 o;
            o.x = acc[i][half * 4 + 0] + bias[n0 + cbase + 0];
            o.y = acc[i][half * 4 + 1] + bias[n0 + cbase + 1];
            o.z = acc[i][half * 4 + 2] + bias[n0 + cbase + 2];
            o.w = acc[i][half * 4 + 3] + bias[n0 + cbase + 3];
            *reinterpret_cast<float4*>(Out + orow + cbase) = o;
        }
    }
}

// Fused QKV projection: blockIdx.z selects (Wq,bq,Q) / (Wk,bk,K) / (Wv,bv,V).
__global__ void __launch_bounds__(256, 2) qkv_gemm_kernel(
    const float* __restrict__ x,
    const float* __restrict__ Wq, const float* __restrict__ bq, float* __restrict__ Q,
    const float* __restrict__ Wk, const float* __restrict__ bk, float* __restrict__ K,
    const float* __restrict__ Wv, const float* __restrict__ bv, float* __restrict__ V)
{
    __shared__ float As[2][16][132];
    __shared__ float Bs[2][16][132];

    const float* B;  const float* bias;  float* Out;
    if (blockIdx.z == 0)      { B = Wq; bias = bq; Out = Q; }
    else if (blockIdx.z == 1) { B = Wk; bias = bk; Out = K; }
    else                      { B = Wv; bias = bv; Out = V; }

    gemm_body(x, B, bias, Out, C_DIM, C_DIM,
              blockIdx.y * 128, blockIdx.x * 128, As, Bs);
}

// Single GEMM (output projection)
__global__ void __launch_bounds__(256, 2) gemm_bias_kernel(
    const float* __restrict__ A, const float* __restrict__ B,
    const float* __restrict__ bias, float* __restrict__ Out)
{
    __shared__ float As[2][16][132];
    __shared__ float Bs[2][16][132];
    gemm_body(A, B, bias, Out, C_DIM, C_DIM,
              blockIdx.y * 128, blockIdx.x * 128, As, Bs);
}

// ---------------------------------------------------------------------------
// Fused per-head RMSNorm + rotary for Q and K.
// ---------------------------------------------------------------------------
__global__ void __launch_bounds__(128) rmsnorm_rope_kernel(
    float* __restrict__ Q, float* __restrict__ K,
    const float* __restrict__ rope,
    const float* __restrict__ qw, const float* __restrict__ kw)
{
    __shared__ float sv[128];
    __shared__ float red[4];

    const int bid = blockIdx.x;
    const int s = bid >> 4;
    const int h = bid & 15;
    const int d = threadIdx.x;
    const int lane = d & 31, wid = d >> 5;
    const size_t idx = (size_t)s * C_DIM + h * D_DIM + d;
    const int p2 = (d >> 1) << 1;
    const float* rp = rope + (size_t)s * 256 + (d >> 1) * 4 + (d & 1) * 2;
    const float r0 = rp[0], r1 = rp[1];

    // ---- Q ----
    {
        float v = Q[idx];
        float ss = v * v;
#pragma unroll
        for (int o = 16; o; o >>= 1) ss += __shfl_xor_sync(0xffffffffu, ss, o);
        if (lane == 0) red[wid] = ss;
        __syncthreads();
        float tot = red[0] + red[1] + red[2] + red[3];
        float inv = rsqrtf(tot * (1.f / 128.f) + EPS_RMS);
        sv[d] = v * inv * qw[d];
        __syncthreads();
        Q[idx] = r0 * sv[p2] + r1 * sv[p2 + 1];
    }
    __syncthreads();
    // ---- K ----
    {
        float v = K[idx];
        float ss = v * v;
#pragma unroll
        for (int o = 16; o; o >>= 1) ss += __shfl_xor_sync(0xffffffffu, ss, o);
        if (lane == 0) red[wid] = ss;
        __syncthreads();
        float tot = red[0] + red[1] + red[2] + red[3];
        float inv = rsqrtf(tot * (1.f / 128.f) + EPS_RMS);
        sv[d] = v * inv * kw[d];
        __syncthreads();
        K[idx] = r0 * sv[p2] + r1 * sv[p2 + 1];
    }
}

// ---------------------------------------------------------------------------
// Flash attention (fp32, online softmax), XOR-swizzled tiles, register softmax.
// __launch_bounds__(256, 2): 2 CTAs/SM (smem 2x83.7KB=167KB < 228KB; regs
// capped at 128, est. usage ~100) -> 4 warps/SMSP for LDS/sync latency hiding.
//
// Tile layout (sQ, sKV): 64 rows x 128 floats, stride 128, 16B chunk cc of
// row r stored at chunk (cc ^ (r & 7)).  Conflict audit per LDS.128 phase:
//  * tile load/store: row fixed per warp, cc = lane -> permuted, distinct.  OK
//  * score qv: row warp-uniform -> broadcast.                              OK
//  * score kv: rows sc+16c: chunk = (kk>>2)^(sc&7) -> 8 distinct quads.    OK
//  * PV vv: row fixed, chunk tc^const -> permuted, distinct.               OK
//  * P scalar stores: lanes 0-15 banks B..B+15, lanes 16-31 B+16..B+31.   OK
//
// Softmax is register-resident: each score row (sr*4+r) is owned by one
// 16-lane group; row max/sum reduce via __shfl_xor {1,2,4,8}.  sS holds only
// the final P.  V global loads issue right after the post-score sync so LDG
// latency overlaps the MUFU-heavy exp work.
// ---------------------------------------------------------------------------
#define FA_SMEM_FLOATS (64 * 128 * 2 + 64 * 68 + 192)
#define FA_SMEM_BYTES  (FA_SMEM_FLOATS * 4)

__device__ __forceinline__ float4 ld_sw(const float* base, int row, int col)
{
    int chunk = ((col >> 2) ^ (row & 7)) << 2;
    return *reinterpret_cast<const float4*>(base + row * 128 + chunk);
}

__global__ void __launch_bounds__(256, 2) flash_attn_kernel(
    const float* __restrict__ Q, const float* __restrict__ K,
    const float* __restrict__ V, float* __restrict__ O)
{
    extern __shared__ float sm[];
    float* sQ  = sm;                    // 64*128 swizzled
    float* sKV = sQ + 64 * 128;         // 64*128 swizzled (K then V)
    float* sS  = sKV + 64 * 128;        // 64*68 (P only)
    float* sM  = sS + 64 * 68;          // 64
    float* sL  = sM + 64;               // 64
    float* sC  = sL + 64;               // 64

    const int tid = threadIdx.x;
    const int h = blockIdx.y;
    const int m0 = blockIdx.x * 64;
    const size_t headOff = (size_t)h * D_DIM;

    // PV / output mapping: 8 row-groups x 32 col-threads (4 cols each)
    const int tr = tid >> 5;   // 0..7
    const int tc = tid & 31;   // 0..31
    // Score mapping: rows sr*4+r (r<4), cols sc + 16*c (c<4)
    const int sr = tid >> 4;   // 0..15
    const int sc = tid & 15;   // 0..15

    // Load Q tile (swizzled)
    for (int t = tid; t < 64 * 32; t += 256) {
        int row = t >> 5;
        int cc  = t & 31;
        float4 q = *reinterpret_cast<const float4*>(
            Q + (size_t)(m0 + row) * C_DIM + headOff + cc * 4);
        *reinterpret_cast<float4*>(&sQ[row * 128 + ((cc ^ (row & 7)) << 2)]) = q;
    }
    if (tid < 64) { sM[tid] = -3.402823466e+38f; sL[tid] = 0.f; }

    float accO[8][4];
#pragma unroll
    for (int r = 0; r < 8; r++)
#pragma unroll
        for (int j = 0; j < 4; j++) accO[r][j] = 0.f;

    __syncthreads();

    const float scale = 0.08838834764831845f;  // 1/sqrt(128)

    for (int n0 = 0; n0 < S_DIM; n0 += 64) {
        // Load K tile (swizzled).  Prior iteration's PV-end sync guarantees
        // sKV is no longer being read.
        for (int t = tid; t < 64 * 32; t += 256) {
            int row = t >> 5;
            int cc  = t & 31;
            float4 kq = *reinterpret_cast<const float4*>(
                K + (size_t)(n0 + row) * C_DIM + headOff + cc * 4);
            *reinterpret_cast<float4*>(&sKV[row * 128 + ((cc ^ (row & 7)) << 2)]) = kq;
        }
        __syncthreads();

        // Scores: 4x4 microtile (cols sc+16c), vectorized over k
        float as[4][4];
#pragma unroll
        for (int r = 0; r < 4; r++)
#pragma unroll
            for (int c = 0; c < 4; c++) as[r][c] = 0.f;

        for (int kk = 0; kk < 128; kk += 4) {
            float4 qv[4], kv[4];
#pragma unroll
            for (int r = 0; r < 4; r++) qv[r] = ld_sw(sQ, sr * 4 + r, kk);
#pragma unroll
            for (int c = 0; c < 4; c++) kv[c] = ld_sw(sKV, sc + 16 * c, kk);
#pragma unroll
            for (int r = 0; r < 4; r++)
#pragma unroll
                for (int c = 0; c < 4; c++) {
                    as[r][c] = fmaf(qv[r].x, kv[c].x, as[r][c]);
                    as[r][c] = fmaf(qv[r].y, kv[c].y, as[r][c]);
                    as[r][c] = fmaf(qv[r].z, kv[c].z, as[r][c]);
                    as[r][c] = fmaf(qv[r].w, kv[c].w, as[r][c]);
                }
        }
        __syncthreads();   // all warps done reading K from sKV

        // Issue V tile loads immediately (overlaps softmax register work)
        for (int t = tid; t < 64 * 32; t += 256) {
            int row = t >> 5;
            int cc  = t & 31;
            float4 vq = *reinterpret_cast<const float4*>(
                V + (size_t)(n0 + row) * C_DIM + headOff + cc * 4);
            *reinterpret_cast<float4*>(&sKV[row * 128 + ((cc ^ (row & 7)) << 2)]) = vq;
        }

        // Register softmax: scale, row max via half-warp shuffles, exp, sum.
#pragma unroll
        for (int r = 0; r < 4; r++) {
            const int row = sr * 4 + r;
            float mx = -3.402823466e+38f;
#pragma unroll
            for (int c = 0; c < 4; c++) {
                as[r][c] *= scale;
                mx = fmaxf(mx, as[r][c]);
            }
#pragma unroll
            for (int o = 1; o < 16; o <<= 1)
                mx = fmaxf(mx, __shfl_xor_sync(0xffffffffu, mx, o));

            float mold = sM[row];                    // broadcast read
            float mnew = fmaxf(mold, mx);
            float sum = 0.f;
#pragma unroll
            for (int c = 0; c < 4; c++) {
                float p = __expf(as[r][c] - mnew);
                as[r][c] = p;
                sum += p;
            }
#pragma unroll
            for (int o = 1; o < 16; o <<= 1)
                sum += __shfl_xor_sync(0xffffffffu, sum, o);

            if (sc == 0) {
                float corr = __expf(mold - mnew);
                sM[row] = mnew;
                sC[row] = corr;
                sL[row] = sL[row] * corr + sum;
            }
            // Store P (conflict-free scalar stores)
#pragma unroll
            for (int c = 0; c < 4; c++)
                sS[row * 68 + sc + 16 * c] = as[r][c];
        }
        __syncthreads();   // P, sM/sC/sL, and V tile all visible

        // Rescale output accumulators
#pragma unroll
        for (int r = 0; r < 8; r++) {
            float c = sC[tr * 8 + r];
#pragma unroll
            for (int j = 0; j < 4; j++) accO[r][j] *= c;
        }

        // O += P @ V : kk blocked by 4, float4 P loads (warp-broadcast)
        for (int kk = 0; kk < 64; kk += 4) {
            float4 vv0 = ld_sw(sKV, kk + 0, tc * 4);
            float4 vv1 = ld_sw(sKV, kk + 1, tc * 4);
            float4 vv2 = ld_sw(sKV, kk + 2, tc * 4);
            float4 vv3 = ld_sw(sKV, kk + 3, tc * 4);
#pragma unroll
            for (int r = 0; r < 8; r++) {
                float4 p4 = *reinterpret_cast<const float4*>(&sS[(tr * 8 + r) * 68 + kk]);
                accO[r][0] = fmaf(p4.x, vv0.x, accO[r][0]);
                accO[r][1] = fmaf(p4.x, vv0.y, accO[r][1]);
                accO[r][2] = fmaf(p4.x, vv0.z, accO[r][2]);
                accO[r][3] = fmaf(p4.x, vv0.w, accO[r][3]);
                accO[r][0] = fmaf(p4.y, vv1.x, accO[r][0]);
                accO[r][1] = fmaf(p4.y, vv1.y, accO[r][1]);
                accO[r][2] = fmaf(p4.y, vv1.z, accO[r][2]);
                accO[r][3] = fmaf(p4.y, vv1.w, accO[r][3]);
                accO[r][0] = fmaf(p4.z, vv2.x, accO[r][0]);
                accO[r][1] = fmaf(p4.z, vv2.y, accO[r][1]);
                accO[r][2] = fmaf(p4.z, vv2.z, accO[r][2]);
                accO[r][3] = fmaf(p4.z, vv2.w, accO[r][3]);
                accO[r][0] = fmaf(p4.w, vv3.x, accO[r][0]);
                accO[r][1] = fmaf(p4.w, vv3.y, accO[r][1]);
                accO[r][2] = fmaf(p4.w, vv3.z, accO[r][2]);
                accO[r][3] = fmaf(p4.w, vv3.w, accO[r][3]);
            }
        }
        __syncthreads();   // PV done: next iter may overwrite sKV/sS
    }

    // Epilogue: divide by l, store
#pragma unroll
    for (int r = 0; r < 8; r++) {
        int row = tr * 8 + r;
        float invl = 1.f / sL[row];
        float4 o;
        o.x = accO[r][0] * invl;
        o.y = accO[r][1] * invl;
        o.z = accO[r][2] * invl;
        o.w = accO[r][3] * invl;
        *reinterpret_cast<float4*>(O + (size_t)(m0 + row) * C_DIM + headOff + tc * 4) = o;
    }
}

// ---------------------------------------------------------------------------
// Launch
// Inputs (metadata order): x, rope, Wq, bq, Wk, bk, Wv, bv, qn_w, kn_w, Wo, bo
// ---------------------------------------------------------------------------
extern "C" void kernel_launch(void* const* d_in, const int* in_sizes, int n_in,
                              void* d_out, int out_size)
{
    const float* x    = (const float*)d_in[0];
    const float* rope = (const float*)d_in[1];
    const float* Wq   = (const float*)d_in[2];
    const float* bq   = (const float*)d_in[3];
    const float* Wk   = (const float*)d_in[4];
    const float* bk   = (const float*)d_in[5];
    const float* Wv   = (const float*)d_in[6];
    const float* bv   = (const float*)d_in[7];
    const float* qn_w = (const float*)d_in[8];
    const float* kn_w = (const float*)d_in[9];
    const float* Wo   = (const float*)d_in[10];
    const float* bo   = (const float*)d_in[11];
    float* out = (float*)d_out;

    float *Qp, *Kp, *Vp, *Op;
    cudaGetSymbolAddress((void**)&Qp, g_Q);
    cudaGetSymbolAddress((void**)&Kp, g_K);
    cudaGetSymbolAddress((void**)&Vp, g_V);
    cudaGetSymbolAddress((void**)&Op, g_O);

    dim3 qkvGrid(C_DIM / 128, S_DIM / 128, 3);   // 1536 blocks
    qkv_gemm_kernel<<<qkvGrid, 256>>>(x, Wq, bq, Qp, Wk, bk, Kp, Wv, bv, Vp);

    rmsnorm_rope_kernel<<<S_DIM * H_DIM, 128>>>(Qp, Kp, rope, qn_w, kn_w);

    cudaFuncSetAttribute(flash_attn_kernel,
                         cudaFuncAttributeMaxDynamicSharedMemorySize, FA_SMEM_BYTES);
    flash_attn_kernel<<<dim3(S_DIM / 64, H_DIM), 256, FA_SMEM_BYTES>>>(Qp, Kp, Vp, Op);

    gemm_bias_kernel<<<dim3(C_DIM / 128, S_DIM / 128), 256>>>(Op, Wo, bo, out);
}

// round 8
// speedup vs baseline: 1.3084x; 1.3084x over previous
#include <cuda_runtime.h>
#include <cuda_bf16.h>
#include <cstdint>

// Problem dims (fixed)
#define S_DIM 4096
#define C_DIM 2048
#define H_DIM 16
#define D_DIM 128
#define EPS_RMS 1.1920929e-07f

// ---------------------------------------------------------------------------
// Scratch (allocation-free rule: __device__ globals)
// ---------------------------------------------------------------------------
__device__ float g_Q[S_DIM * C_DIM];
__device__ float g_K[S_DIM * C_DIM];
__device__ float g_V[S_DIM * C_DIM];
__device__ float g_O[S_DIM * C_DIM];

// ---------------------------------------------------------------------------
// tf32 helpers
// ---------------------------------------------------------------------------
__device__ __forceinline__ uint32_t f32_to_tf32(float f)
{
    uint32_t u;
    asm("cvt.rna.tf32.f32 %0, %1;" : "=r"(u) : "f"(f));
    return u;
}

__device__ __forceinline__ void mma_tf32(float* d, const uint32_t* a,
                                         uint32_t b0, uint32_t b1)
{
    asm("mma.sync.aligned.m16n8k8.row.col.f32.tf32.tf32.f32 "
        "{%0,%1,%2,%3}, {%4,%5,%6,%7}, {%8,%9}, {%0,%1,%2,%3};"
        : "+f"(d[0]), "+f"(d[1]), "+f"(d[2]), "+f"(d[3])
        : "r"(a[0]), "r"(a[1]), "r"(a[2]), "r"(a[3]), "r"(b0), "r"(b1));
}

// ---------------------------------------------------------------------------
// tf32 tensor-core GEMM: Out[M,N] = A[M,K] @ B[N,K]^T + bias[N]
// 128x128 block tile, BK=16, 256 threads = 8 warps in 4(M) x 2(N) grid.
// Each warp: 32x64 output = 2 mtiles(16) x 8 ntiles(8), mma.m16n8k8.
//
// Smem layout (per operand, per buffer): [kc][m][klow], kc = k>>2 (0..3),
// klow = k&3, with XOR swizzle on m: stored column = m ^ (kc<<1).
// Conflict audit:
//  * STS.128 (thread: kc = idx&3, m = idx>>2): 16B-quad =
//    (m ^ 2kc) mod 8 -> per 8-lane phase all distinct.   conflict-free
//  * LDS fragment (a0: k = 4*kc + lane%4, m = mb + lane/4): bank =
//    4*((mb+lane/4)^2kc) + lane%4 -> 32 distinct.         conflict-free
// Inputs converted to tf32 at STS time (reused 8-16x from smem).
// ---------------------------------------------------------------------------
__device__ __forceinline__ void sts_tf32(float (*T)[128][4], int kc, int m, float4 v)
{
    float4 w;
    w.x = __uint_as_float(f32_to_tf32(v.x));
    w.y = __uint_as_float(f32_to_tf32(v.y));
    w.z = __uint_as_float(f32_to_tf32(v.z));
    w.w = __uint_as_float(f32_to_tf32(v.w));
    *reinterpret_cast<float4*>(&T[kc][m ^ (kc << 1)][0]) = w;
}

__device__ __forceinline__ void gemm_body_tf32(
    const float* __restrict__ A, const float* __restrict__ B,
    const float* __restrict__ bias, float* __restrict__ Out,
    int K, int N, int m0, int n0,
    float (*As)[4][128][4], float (*Bs)[4][128][4])   // [2 buf][kc][m][klow]
{
    const int tid    = threadIdx.x;
    const int lane   = tid & 31;
    const int wid    = tid >> 5;
    const int warp_m = wid & 3;    // 0..3 -> 32 M-rows each
    const int warp_n = wid >> 2;   // 0..1 -> 64 N-cols each
    const int klow   = lane & 3;
    const int qrow   = lane >> 2;  // 0..7

    float acc[2][8][4];
#pragma unroll
    for (int mt = 0; mt < 2; mt++)
#pragma unroll
        for (int nt = 0; nt < 8; nt++)
#pragma unroll
            for (int i = 0; i < 4; i++) acc[mt][nt][i] = 0.f;

    const float* Aptr = A + (size_t)m0 * K;
    const float* Bptr = B + (size_t)n0 * K;

    // Global-load mapping: idx = tid + r*256; m = idx>>2, kc = idx&3.
    int lm[2], lkc[2];
#pragma unroll
    for (int r = 0; r < 2; r++) {
        int idx = tid + r * 256;
        lm[r]  = idx >> 2;
        lkc[r] = idx & 3;
    }

    // Prologue: first tile into buffer 0
#pragma unroll
    for (int r = 0; r < 2; r++) {
        float4 av = *reinterpret_cast<const float4*>(Aptr + (size_t)lm[r] * K + lkc[r] * 4);
        sts_tf32(As[0], lkc[r], lm[r], av);
        float4 bv = *reinterpret_cast<const float4*>(Bptr + (size_t)lm[r] * K + lkc[r] * 4);
        sts_tf32(Bs[0], lkc[r], lm[r], bv);
    }
    __syncthreads();

    int buf = 0;
    for (int k0 = 0; k0 < K; k0 += 16) {
        const int kn = k0 + 16;
        float4 pa[2], pb[2];
        if (kn < K) {
#pragma unroll
            for (int r = 0; r < 2; r++) {
                pa[r] = *reinterpret_cast<const float4*>(Aptr + (size_t)lm[r] * K + kn + lkc[r] * 4);
                pb[r] = *reinterpret_cast<const float4*>(Bptr + (size_t)lm[r] * K + kn + lkc[r] * 4);
            }
        }

        const float* fA = &As[buf][0][0][0];
        const float* fB = &Bs[buf][0][0][0];
#pragma unroll
        for (int ks = 0; ks < 2; ks++) {          // two k=8 steps per BK16
            const int kc0 = ks * 2, kc1 = kc0 + 1;
            uint32_t a[2][4];
#pragma unroll
            for (int mt = 0; mt < 2; mt++) {
                int mb = warp_m * 32 + mt * 16 + qrow;
                a[mt][0] = __float_as_uint(fA[(kc0 * 128 + ((mb)     ^ (kc0 << 1))) * 4 + klow]);
                a[mt][1] = __float_as_uint(fA[(kc0 * 128 + ((mb + 8) ^ (kc0 << 1))) * 4 + klow]);
                a[mt][2] = __float_as_uint(fA[(kc1 * 128 + ((mb)     ^ (kc1 << 1))) * 4 + klow]);
                a[mt][3] = __float_as_uint(fA[(kc1 * 128 + ((mb + 8) ^ (kc1 << 1))) * 4 + klow]);
            }
#pragma unroll
            for (int nt = 0; nt < 8; nt++) {
                int nb = warp_n * 64 + nt * 8 + qrow;
                uint32_t b0 = __float_as_uint(fB[(kc0 * 128 + (nb ^ (kc0 << 1))) * 4 + klow]);
                uint32_t b1 = __float_as_uint(fB[(kc1 * 128 + (nb ^ (kc1 << 1))) * 4 + klow]);
                mma_tf32(acc[0][nt], a[0], b0, b1);
                mma_tf32(acc[1][nt], a[1], b0, b1);
            }
        }

        if (kn < K) {
            const int nb = buf ^ 1;   // ping-pong: no race with readers of buf
#pragma unroll
            for (int r = 0; r < 2; r++) {
                sts_tf32(As[nb], lkc[r], lm[r], pa[r]);
                sts_tf32(Bs[nb], lkc[r], lm[r], pb[r]);
            }
        }
        __syncthreads();
        buf ^= 1;
    }

    // Epilogue: bias add, float2 stores.
    // d0,d1 -> row lane/4,   cols 2*(lane%4), +1
    // d2,d3 -> row lane/4+8, same cols
#pragma unroll
    for (int nt = 0; nt < 8; nt++) {
        int gn = n0 + warp_n * 64 + nt * 8 + 2 * klow;
        float2 bv = *reinterpret_cast<const float2*>(&bias[gn]);
#pragma unroll
        for (int mt = 0; mt < 2; mt++) {
            int gm0 = m0 + warp_m * 32 + mt * 16 + qrow;
            float2 o0, o1;
            o0.x = acc[mt][nt][0] + bv.x;  o0.y = acc[mt][nt][1] + bv.y;
            o1.x = acc[mt][nt][2] + bv.x;  o1.y = acc[mt][nt][3] + bv.y;
            *reinterpret_cast<float2*>(Out + (size_t)gm0 * N + gn) = o0;
            *reinterpret_cast<float2*>(Out + (size_t)(gm0 + 8) * N + gn) = o1;
        }
    }
}

// Fused QKV projection: blockIdx.z selects (Wq,bq,Q) / (Wk,bk,K) / (Wv,bv,V).
__global__ void __launch_bounds__(256, 2) qkv_gemm_kernel(
    const float* __restrict__ x,
    const float* __restrict__ Wq, const float* __restrict__ bq, float* __restrict__ Q,
    const float* __restrict__ Wk, const float* __restrict__ bk, float* __restrict__ K,
    const float* __restrict__ Wv, const float* __restrict__ bv, float* __restrict__ V)
{
    __shared__ float As[2][4][128][4];
    __shared__ float Bs[2][4][128][4];

    const float* B;  const float* bias;  float* Out;
    if (blockIdx.z == 0)      { B = Wq; bias = bq; Out = Q; }
    else if (blockIdx.z == 1) { B = Wk; bias = bk; Out = K; }
    else                      { B = Wv; bias = bv; Out = V; }

    gemm_body_tf32(x, B, bias, Out, C_DIM, C_DIM,
                   blockIdx.y * 128, blockIdx.x * 128, As, Bs);
}

// Single GEMM (output projection)
__global__ void __launch_bounds__(256, 2) gemm_bias_kernel(
    const float* __restrict__ A, const float* __restrict__ B,
    const float* __restrict__ bias, float* __restrict__ Out)
{
    __shared__ float As[2][4][128][4];
    __shared__ float Bs[2][4][128][4];
    gemm_body_tf32(A, B, bias, Out, C_DIM, C_DIM,
                   blockIdx.y * 128, blockIdx.x * 128, As, Bs);
}

// ---------------------------------------------------------------------------
// Fused per-head RMSNorm + rotary for Q and K.  (unchanged, verified)
// ---------------------------------------------------------------------------
__global__ void __launch_bounds__(128) rmsnorm_rope_kernel(
    float* __restrict__ Q, float* __restrict__ K,
    const float* __restrict__ rope,
    const float* __restrict__ qw, const float* __restrict__ kw)
{
    __shared__ float sv[128];
    __shared__ float red[4];

    const int bid = blockIdx.x;
    const int s = bid >> 4;
    const int h = bid & 15;
    const int d = threadIdx.x;
    const int lane = d & 31, wid = d >> 5;
    const size_t idx = (size_t)s * C_DIM + h * D_DIM + d;
    const int p2 = (d >> 1) << 1;
    const float* rp = rope + (size_t)s * 256 + (d >> 1) * 4 + (d & 1) * 2;
    const float r0 = rp[0], r1 = rp[1];

    // ---- Q ----
    {
        float v = Q[idx];
        float ss = v * v;
#pragma unroll
        for (int o = 16; o; o >>= 1) ss += __shfl_xor_sync(0xffffffffu, ss, o);
        if (lane == 0) red[wid] = ss;
        __syncthreads();
        float tot = red[0] + red[1] + red[2] + red[3];
        float inv = rsqrtf(tot * (1.f / 128.f) + EPS_RMS);
        sv[d] = v * inv * qw[d];
        __syncthreads();
        Q[idx] = r0 * sv[p2] + r1 * sv[p2 + 1];
    }
    __syncthreads();
    // ---- K ----
    {
        float v = K[idx];
        float ss = v * v;
#pragma unroll
        for (int o = 16; o; o >>= 1) ss += __shfl_xor_sync(0xffffffffu, ss, o);
        if (lane == 0) red[wid] = ss;
        __syncthreads();
        float tot = red[0] + red[1] + red[2] + red[3];
        float inv = rsqrtf(tot * (1.f / 128.f) + EPS_RMS);
        sv[d] = v * inv * kw[d];
        __syncthreads();
        K[idx] = r0 * sv[p2] + r1 * sv[p2 + 1];
    }
}

// ---------------------------------------------------------------------------
// Flash attention (fp32, online softmax), XOR-swizzled tiles, register softmax.
// (unchanged from the round-7 PASSING version)
// ---------------------------------------------------------------------------
#define FA_SMEM_FLOATS (64 * 128 * 2 + 64 * 68 + 192)
#define FA_SMEM_BYTES  (FA_SMEM_FLOATS * 4)

__device__ __forceinline__ float4 ld_sw(const float* base, int row, int col)
{
    int chunk = ((col >> 2) ^ (row & 7)) << 2;
    return *reinterpret_cast<const float4*>(base + row * 128 + chunk);
}

__global__ void __launch_bounds__(256, 2) flash_attn_kernel(
    const float* __restrict__ Q, const float* __restrict__ K,
    const float* __restrict__ V, float* __restrict__ O)
{
    extern __shared__ float sm[];
    float* sQ  = sm;                    // 64*128 swizzled
    float* sKV = sQ + 64 * 128;         // 64*128 swizzled (K then V)
    float* sS  = sKV + 64 * 128;        // 64*68 (P only)
    float* sM  = sS + 64 * 68;          // 64
    float* sL  = sM + 64;               // 64
    float* sC  = sL + 64;               // 64

    const int tid = threadIdx.x;
    const int h = blockIdx.y;
    const int m0 = blockIdx.x * 64;
    const size_t headOff = (size_t)h * D_DIM;

    const int tr = tid >> 5;   // 0..7
    const int tc = tid & 31;   // 0..31
    const int sr = tid >> 4;   // 0..15
    const int sc = tid & 15;   // 0..15

    for (int t = tid; t < 64 * 32; t += 256) {
        int row = t >> 5;
        int cc  = t & 31;
        float4 q = *reinterpret_cast<const float4*>(
            Q + (size_t)(m0 + row) * C_DIM + headOff + cc * 4);
        *reinterpret_cast<float4*>(&sQ[row * 128 + ((cc ^ (row & 7)) << 2)]) = q;
    }
    if (tid < 64) { sM[tid] = -3.402823466e+38f; sL[tid] = 0.f; }

    float accO[8][4];
#pragma unroll
    for (int r = 0; r < 8; r++)
#pragma unroll
        for (int j = 0; j < 4; j++) accO[r][j] = 0.f;

    __syncthreads();

    const float scale = 0.08838834764831845f;  // 1/sqrt(128)

    for (int n0 = 0; n0 < S_DIM; n0 += 64) {
        for (int t = tid; t < 64 * 32; t += 256) {
            int row = t >> 5;
            int cc  = t & 31;
            float4 kq = *reinterpret_cast<const float4*>(
                K + (size_t)(n0 + row) * C_DIM + headOff + cc * 4);
            *reinterpret_cast<float4*>(&sKV[row * 128 + ((cc ^ (row & 7)) << 2)]) = kq;
        }
        __syncthreads();

        float as[4][4];
#pragma unroll
        for (int r = 0; r < 4; r++)
#pragma unroll
            for (int c = 0; c < 4; c++) as[r][c] = 0.f;

        for (int kk = 0; kk < 128; kk += 4) {
            float4 qv[4], kv[4];
#pragma unroll
            for (int r = 0; r < 4; r++) qv[r] = ld_sw(sQ, sr * 4 + r, kk);
#pragma unroll
            for (int c = 0; c < 4; c++) kv[c] = ld_sw(sKV, sc + 16 * c, kk);
#pragma unroll
            for (int r = 0; r < 4; r++)
#pragma unroll
                for (int c = 0; c < 4; c++) {
                    as[r][c] = fmaf(qv[r].x, kv[c].x, as[r][c]);
                    as[r][c] = fmaf(qv[r].y, kv[c].y, as[r][c]);
                    as[r][c] = fmaf(qv[r].z, kv[c].z, as[r][c]);
                    as[r][c] = fmaf(qv[r].w, kv[c].w, as[r][c]);
                }
        }
        __syncthreads();   // all warps done reading K from sKV

        for (int t = tid; t < 64 * 32; t += 256) {
            int row = t >> 5;
            int cc  = t & 31;
            float4 vq = *reinterpret_cast<const float4*>(
                V + (size_t)(n0 + row) * C_DIM + headOff + cc * 4);
            *reinterpret_cast<float4*>(&sKV[row * 128 + ((cc ^ (row & 7)) << 2)]) = vq;
        }

        // Register softmax via half-warp shuffles
#pragma unroll
        for (int r = 0; r < 4; r++) {
            const int row = sr * 4 + r;
            float mx = -3.402823466e+38f;
#pragma unroll
            for (int c = 0; c < 4; c++) {
                as[r][c] *= scale;
                mx = fmaxf(mx, as[r][c]);
            }
#pragma unroll
            for (int o = 1; o < 16; o <<= 1)
                mx = fmaxf(mx, __shfl_xor_sync(0xffffffffu, mx, o));

            float mold = sM[row];
            float mnew = fmaxf(mold, mx);
            float sum = 0.f;
#pragma unroll
            for (int c = 0; c < 4; c++) {
                float p = __expf(as[r][c] - mnew);
                as[r][c] = p;
                sum += p;
            }
#pragma unroll
            for (int o = 1; o < 16; o <<= 1)
                sum += __shfl_xor_sync(0xffffffffu, sum, o);

            if (sc == 0) {
                float corr = __expf(mold - mnew);
                sM[row] = mnew;
                sC[row] = corr;
                sL[row] = sL[row] * corr + sum;
            }
#pragma unroll
            for (int c = 0; c < 4; c++)
                sS[row * 68 + sc + 16 * c] = as[r][c];
        }
        __syncthreads();   // P, sM/sC/sL, and V tile all visible

#pragma unroll
        for (int r = 0; r < 8; r++) {
            float c = sC[tr * 8 + r];
#pragma unroll
            for (int j = 0; j < 4; j++) accO[r][j] *= c;
        }

        for (int kk = 0; kk < 64; kk += 4) {
            float4 vv0 = ld_sw(sKV, kk + 0, tc * 4);
            float4 vv1 = ld_sw(sKV, kk + 1, tc * 4);
            float4 vv2 = ld_sw(sKV, kk + 2, tc * 4);
            float4 vv3 = ld_sw(sKV, kk + 3, tc * 4);
#pragma unroll
            for (int r = 0; r < 8; r++) {
                float4 p4 = *reinterpret_cast<const float4*>(&sS[(tr * 8 + r) * 68 + kk]);
                accO[r][0] = fmaf(p4.x, vv0.x, accO[r][0]);
                accO[r][1] = fmaf(p4.x, vv0.y, accO[r][1]);
                accO[r][2] = fmaf(p4.x, vv0.z, accO[r][2]);
                accO[r][3] = fmaf(p4.x, vv0.w, accO[r][3]);
                accO[r][0] = fmaf(p4.y, vv1.x, accO[r][0]);
                accO[r][1] = fmaf(p4.y, vv1.y, accO[r][1]);
                accO[r][2] = fmaf(p4.y, vv1.z, accO[r][2]);
                accO[r][3] = fmaf(p4.y, vv1.w, accO[r][3]);
                accO[r][0] = fmaf(p4.z, vv2.x, accO[r][0]);
                accO[r][1] = fmaf(p4.z, vv2.y, accO[r][1]);
                accO[r][2] = fmaf(p4.z, vv2.z, accO[r][2]);
                accO[r][3] = fmaf(p4.z, vv2.w, accO[r][3]);
                accO[r][0] = fmaf(p4.w, vv3.x, accO[r][0]);
                accO[r][1] = fmaf(p4.w, vv3.y, accO[r][1]);
                accO[r][2] = fmaf(p4.w, vv3.z, accO[r][2]);
                accO[r][3] = fmaf(p4.w, vv3.w, accO[r][3]);
            }
        }
        __syncthreads();   // PV done: next iter may overwrite sKV/sS
    }

#pragma unroll
    for (int r = 0; r < 8; r++) {
        int row = tr * 8 + r;
        float invl = 1.f / sL[row];
        float4 o;
        o.x = accO[r][0] * invl;
        o.y = accO[r][1] * invl;
        o.z = accO[r][2] * invl;
        o.w = accO[r][3] * invl;
        *reinterpret_cast<float4*>(O + (size_t)(m0 + row) * C_DIM + headOff + tc * 4) = o;
    }
}

// ---------------------------------------------------------------------------
// Launch
// Inputs (metadata order): x, rope, Wq, bq, Wk, bk, Wv, bv, qn_w, kn_w, Wo, bo
// ---------------------------------------------------------------------------
extern "C" void kernel_launch(void* const* d_in, const int* in_sizes, int n_in,
                              void* d_out, int out_size)
{
    const float* x    = (const float*)d_in[0];
    const float* rope = (const float*)d_in[1];
    const float* Wq   = (const float*)d_in[2];
    const float* bq   = (const float*)d_in[3];
    const float* Wk   = (const float*)d_in[4];
    const float* bk   = (const float*)d_in[5];
    const float* Wv   = (const float*)d_in[6];
    const float* bv   = (const float*)d_in[7];
    const float* qn_w = (const float*)d_in[8];
    const float* kn_w = (const float*)d_in[9];
    const float* Wo   = (const float*)d_in[10];
    const float* bo   = (const float*)d_in[11];
    float* out = (float*)d_out;

    float *Qp, *Kp, *Vp, *Op;
    cudaGetSymbolAddress((void**)&Qp, g_Q);
    cudaGetSymbolAddress((void**)&Kp, g_K);
    cudaGetSymbolAddress((void**)&Vp, g_V);
    cudaGetSymbolAddress((void**)&Op, g_O);

    dim3 qkvGrid(C_DIM / 128, S_DIM / 128, 3);   // 1536 blocks
    qkv_gemm_kernel<<<qkvGrid, 256>>>(x, Wq, bq, Qp, Wk, bk, Kp, Wv, bv, Vp);

    rmsnorm_rope_kernel<<<S_DIM * H_DIM, 128>>>(Qp, Kp, rope, qn_w, kn_w);

    cudaFuncSetAttribute(flash_attn_kernel,
                         cudaFuncAttributeMaxDynamicSharedMemorySize, FA_SMEM_BYTES);
    flash_attn_kernel<<<dim3(S_DIM / 64, H_DIM), 256, FA_SMEM_BYTES>>>(Qp, Kp, Vp, Op);

    gemm_bias_kernel<<<dim3(C_DIM / 128, S_DIM / 128), 256>>>(Op, Wo, bo, out);
}